// round 2
// baseline (speedup 1.0000x reference)
#include <cuda_runtime.h>
#include <math.h>

#define DIMV 640
#define MS 100
#define NB 64
#define BK 64
#define KT 50
#define NTILE 10                 // DIMV / BK
#define OUT_PER_B 205120         // 640*641/2
#define EPSV 1e-5f

// Scratch (allocation-free rule: __device__ globals)
__device__ float g_dcov[(size_t)NB * DIMV * DIMV];   // 105 MB
__device__ float g_d[NB * DIMV];                     // squared norms (Gram diag)
__device__ float g_s[NB * DIMV];                     // row sums of dcov
__device__ float g_grand[NB];                        // grand sums
__device__ float g_et;                               // exp(t)

// ---------------------------------------------------------------------------
// K0: per-row squared norms d[b][i] = sum_m x[b][i][m]^2 ; also exp(t)
// One warp per row. 8 warps per block, 5120 blocks.
// ---------------------------------------------------------------------------
__global__ void k_prep(const float* __restrict__ x, const float* __restrict__ t) {
    if (blockIdx.x == 0 && threadIdx.x == 0) g_et = expf(t[0]);
    int warp = blockIdx.x * 8 + (threadIdx.x >> 5);
    int lane = threadIdx.x & 31;
    if (warp >= NB * DIMV) return;
    const float* row = x + (size_t)warp * MS;
    float s = 0.f;
    // MS = 100: lanes cover 0..95 in 3 strides + tail 96..99
    s += row[lane];
    s += row[lane + 32];
    s += row[lane + 64];
    float v3 = (lane < 4) ? row[lane + 96] : 0.f;
    s = s * 0.f; // (overwritten below — keep compiler honest) 
    // recompute properly with squares:
    float a0 = row[lane], a1 = row[lane + 32], a2 = row[lane + 64];
    s = a0 * a0 + a1 * a1 + a2 * a2 + v3 * v3;
    #pragma unroll
    for (int off = 16; off > 0; off >>= 1)
        s += __shfl_down_sync(0xffffffffu, s, off);
    if (lane == 0) g_d[warp] = s;
}

// ---------------------------------------------------------------------------
// K1: per batch, upper-triangle 64x64 tiles of Gram; fused dcov transform.
// grid = (55, NB), block = 256 (16x16 threads, 4x4 micro-tile each).
// smem [k][row] layout so compute reads are float4 / broadcast.
// ---------------------------------------------------------------------------
__global__ void __launch_bounds__(256, 2) k_gemm_dcov(const float* __restrict__ x) {
    __shared__ float As[KT][BK + 4];
    __shared__ float Bs[KT][BK + 4];

    const int b = blockIdx.y;
    // map linear upper-tri tile index -> (ti, tj), ti <= tj
    int ti = 0, rem = blockIdx.x, cnt = NTILE;
    while (rem >= cnt) { rem -= cnt; cnt--; ti++; }
    const int tj = ti + rem;

    const int i0 = ti * BK, j0 = tj * BK;
    const float* xb = x + (size_t)b * DIMV * MS;
    const int tid = threadIdx.x;
    const int tx = tid & 15, ty = tid >> 4;

    float c[4][4];
    #pragma unroll
    for (int u = 0; u < 4; u++)
        #pragma unroll
        for (int v = 0; v < 4; v++) c[u][v] = 0.f;

    for (int kc = 0; kc < MS; kc += KT) {
        // coalesced global reads (row-major over the KT-wide k-slab)
        for (int idx = tid; idx < BK * KT; idx += 256) {
            int rr = idx / KT, kk = idx % KT;
            As[kk][rr] = xb[(size_t)(i0 + rr) * MS + kc + kk];
            Bs[kk][rr] = xb[(size_t)(j0 + rr) * MS + kc + kk];
        }
        __syncthreads();
        #pragma unroll 10
        for (int k = 0; k < KT; k++) {
            float4 av = *(const float4*)&As[k][ty * 4];
            float4 bv = *(const float4*)&Bs[k][tx * 4];
            c[0][0] += av.x * bv.x; c[0][1] += av.x * bv.y; c[0][2] += av.x * bv.z; c[0][3] += av.x * bv.w;
            c[1][0] += av.y * bv.x; c[1][1] += av.y * bv.y; c[1][2] += av.y * bv.z; c[1][3] += av.y * bv.w;
            c[2][0] += av.z * bv.x; c[2][1] += av.z * bv.y; c[2][2] += av.z * bv.z; c[2][3] += av.z * bv.w;
            c[3][0] += av.w * bv.x; c[3][1] += av.w * bv.y; c[3][2] += av.w * bv.z; c[3][3] += av.w * bv.w;
        }
        __syncthreads();
    }

    // epilogue: dcov = sqrt(et * max(d_i + d_j - 2*G, 0) + eps)
    const float et = g_et;
    const float* dv = g_d + b * DIMV;
    float di[4], dj[4];
    #pragma unroll
    for (int u = 0; u < 4; u++) di[u] = dv[i0 + ty * 4 + u];
    #pragma unroll
    for (int v = 0; v < 4; v++) dj[v] = dv[j0 + tx * 4 + v];

    float* dc = g_dcov + (size_t)b * DIMV * DIMV;
    #pragma unroll
    for (int u = 0; u < 4; u++) {
        const int i = i0 + ty * 4 + u;
        float4 row;
        float vals[4];
        #pragma unroll
        for (int v = 0; v < 4; v++) {
            float arg = et * fmaxf(di[u] + dj[v] - 2.f * c[u][v], 0.f) + EPSV;
            vals[v] = sqrtf(arg);
        }
        row.x = vals[0]; row.y = vals[1]; row.z = vals[2]; row.w = vals[3];
        *(float4*)&dc[(size_t)i * DIMV + j0 + tx * 4] = row;   // coalesced main store
        if (ti != tj) {
            #pragma unroll
            for (int v = 0; v < 4; v++) {
                const int j = j0 + tx * 4 + v;
                dc[(size_t)j * DIMV + i] = vals[v];            // mirrored (scatter, L2 absorbs)
            }
        }
    }
}

// ---------------------------------------------------------------------------
// K2: row sums of dcov (symmetric -> row sum == col sum). One warp per row.
// ---------------------------------------------------------------------------
__global__ void k_rowsum() {
    int warp = blockIdx.x * 8 + (threadIdx.x >> 5);
    int lane = threadIdx.x & 31;
    if (warp >= NB * DIMV) return;
    const float* row = g_dcov + (size_t)warp * DIMV;
    float s = 0.f;
    #pragma unroll
    for (int j = 0; j < DIMV; j += 32) s += row[j + lane];
    #pragma unroll
    for (int off = 16; off > 0; off >>= 1)
        s += __shfl_down_sync(0xffffffffu, s, off);
    if (lane == 0) g_s[warp] = s;
}

// ---------------------------------------------------------------------------
// K3: grand sum per batch = sum_i s[b][i]. One block per batch.
// ---------------------------------------------------------------------------
__global__ void k_grand() {
    __shared__ float sh[256];
    const int b = blockIdx.x;
    const int tid = threadIdx.x;
    float s = 0.f;
    for (int i = tid; i < DIMV; i += 256) s += g_s[b * DIMV + i];
    sh[tid] = s;
    __syncthreads();
    for (int off = 128; off > 0; off >>= 1) {
        if (tid < off) sh[tid] += sh[tid + off];
        __syncthreads();
    }
    if (tid == 0) g_grand[b] = sh[0];
}

// ---------------------------------------------------------------------------
// K4: double-center + triu extraction. grid (DIMV, NB), block 256.
// out[b][triu(i,j)] = dcov - (s_i + s_j)/dim + grand/dim^2
// ---------------------------------------------------------------------------
__global__ void k_out(float* __restrict__ out) {
    const int i = blockIdx.x;
    const int b = blockIdx.y;
    const float inv = 1.f / (float)DIMV;
    const float inv2 = inv * inv;
    const float si = g_s[b * DIMV + i];
    const float gm = g_grand[b] * inv2;
    const float* drow = g_dcov + (size_t)b * DIMV * DIMV + (size_t)i * DIMV;
    const float* sv = g_s + b * DIMV;
    // triu row start: sum_{r<i} (DIMV - r) = i*DIMV - i*(i-1)/2
    const size_t base = (size_t)b * OUT_PER_B + (size_t)i * DIMV - (size_t)i * (i - 1) / 2;
    for (int j = i + threadIdx.x; j < DIMV; j += 256) {
        float v = drow[j] - (si + sv[j]) * inv + gm;
        out[base + (j - i)] = v;
    }
}

// ---------------------------------------------------------------------------
extern "C" void kernel_launch(void* const* d_in, const int* in_sizes, int n_in,
                              void* d_out, int out_size) {
    const float* x = (const float*)d_in[0];
    const float* t = (const float*)d_in[1];
    float* out = (float*)d_out;

    k_prep<<<(NB * DIMV) / 8, 256>>>(x, t);
    k_gemm_dcov<<<dim3(55, NB), 256>>>(x);
    k_rowsum<<<(NB * DIMV) / 8, 256>>>();
    k_grand<<<NB, 256>>>();
    k_out<<<dim3(DIMV, NB), 256>>>(out);
}

// round 5
// speedup vs baseline: 1.2660x; 1.2660x over previous
#include <cuda_runtime.h>
#include <math.h>

#define DIMV 640
#define MS 100
#define NB 64
#define BK 64
#define KT 50
#define NTILE 10                 // DIMV / BK
#define OUT_PER_B 205120         // 640*641/2
#define EPSV 1e-5f

// Scratch (allocation-free rule: __device__ globals)
__device__ float g_d[NB * DIMV];                     // squared norms (Gram diag)
__device__ float g_s[NB * DIMV];                     // row sums of dcov (atomic accum)
__device__ float g_grand[NB];                        // grand sums
__device__ float g_et;                               // exp(t)

// packed-triu row start of (i,i): i*DIMV - i*(i-1)/2
__device__ __forceinline__ size_t triu_start(int i) {
    return (size_t)i * DIMV - ((size_t)i * (i - 1)) / 2;
}

// ---------------------------------------------------------------------------
// K0: per-row squared norms d[b][i] = sum_m x[b][i][m]^2 ; exp(t); zero g_s.
// One warp per row. 8 warps per block, 5120 blocks.
// ---------------------------------------------------------------------------
__global__ void k_prep(const float* __restrict__ x, const float* __restrict__ t) {
    if (blockIdx.x == 0 && threadIdx.x == 0) g_et = expf(t[0]);
    int gtid = blockIdx.x * 256 + threadIdx.x;
    if (gtid < NB * DIMV) g_s[gtid] = 0.f;           // reset accumulators each replay

    int warp = blockIdx.x * 8 + (threadIdx.x >> 5);
    int lane = threadIdx.x & 31;
    if (warp >= NB * DIMV) return;
    const float* row = x + (size_t)warp * MS;
    float a0 = row[lane], a1 = row[lane + 32], a2 = row[lane + 64];
    float a3 = (lane < 4) ? row[lane + 96] : 0.f;
    float s = a0 * a0 + a1 * a1 + a2 * a2 + a3 * a3;
    #pragma unroll
    for (int off = 16; off > 0; off >>= 1)
        s += __shfl_down_sync(0xffffffffu, s, off);
    if (lane == 0) g_d[warp] = s;
}

// ---------------------------------------------------------------------------
// K1: per batch, upper-triangle 64x64 tiles of Gram; fused dcov transform,
// packed-triu store into out (uncentered), fused row/col-sum accumulation.
// grid = (55, NB), block = 256 (16x16 threads, 4x4 micro-tile each).
// ---------------------------------------------------------------------------
__global__ void __launch_bounds__(256, 2) k_gemm_dcov(const float* __restrict__ x,
                                                      float* __restrict__ out) {
    __shared__ float As[KT][BK + 4];
    __shared__ float Bs[KT][BK + 4];

    const int b = blockIdx.y;
    // map linear upper-tri tile index -> (ti, tj), ti <= tj
    int ti = 0, rem = blockIdx.x, cnt = NTILE;
    while (rem >= cnt) { rem -= cnt; cnt--; ti++; }
    const int tj = ti + rem;

    const int i0 = ti * BK, j0 = tj * BK;
    const float* xb = x + (size_t)b * DIMV * MS;
    const int tid = threadIdx.x;
    const int tx = tid & 15, ty = tid >> 4;

    float c[4][4];
    #pragma unroll
    for (int u = 0; u < 4; u++)
        #pragma unroll
        for (int v = 0; v < 4; v++) c[u][v] = 0.f;

    for (int kc = 0; kc < MS; kc += KT) {
        for (int idx = tid; idx < BK * KT; idx += 256) {
            int rr = idx / KT, kk = idx % KT;
            As[kk][rr] = xb[(size_t)(i0 + rr) * MS + kc + kk];
            Bs[kk][rr] = xb[(size_t)(j0 + rr) * MS + kc + kk];
        }
        __syncthreads();
        #pragma unroll 10
        for (int k = 0; k < KT; k++) {
            float4 av = *(const float4*)&As[k][ty * 4];
            float4 bv = *(const float4*)&Bs[k][tx * 4];
            c[0][0] += av.x * bv.x; c[0][1] += av.x * bv.y; c[0][2] += av.x * bv.z; c[0][3] += av.x * bv.w;
            c[1][0] += av.y * bv.x; c[1][1] += av.y * bv.y; c[1][2] += av.y * bv.z; c[1][3] += av.y * bv.w;
            c[2][0] += av.z * bv.x; c[2][1] += av.z * bv.y; c[2][2] += av.z * bv.z; c[2][3] += av.z * bv.w;
            c[3][0] += av.w * bv.x; c[3][1] += av.w * bv.y; c[3][2] += av.w * bv.z; c[3][3] += av.w * bv.w;
        }
        __syncthreads();
    }

    // reduction scratch carved out of As (done with it now)
    float* sr = &As[0][0];        // 64: row sums of this tile (direct store)
    float* sc = sr + 64;          // 64: col sums of this tile (atomic)
    if (tid < 64) sc[tid] = 0.f;
    __syncthreads();

    // epilogue: dcov = sqrt(et * max(d_i + d_j - 2*G, 0) + eps)
    const float et = g_et;
    const float* dv = g_d + b * DIMV;
    float di[4], dj[4];
    #pragma unroll
    for (int u = 0; u < 4; u++) di[u] = dv[i0 + ty * 4 + u];
    #pragma unroll
    for (int v = 0; v < 4; v++) dj[v] = dv[j0 + tx * 4 + v];

    const size_t ob = (size_t)b * OUT_PER_B;
    const bool diag = (ti == tj);
    float colpart[4] = {0.f, 0.f, 0.f, 0.f};

    #pragma unroll
    for (int u = 0; u < 4; u++) {
        const int i = i0 + ty * 4 + u;
        float vals[4];
        float rowpart = 0.f;
        #pragma unroll
        for (int v = 0; v < 4; v++) {
            float arg = et * fmaxf(di[u] + dj[v] - 2.f * c[u][v], 0.f) + EPSV;
            vals[v] = sqrtf(arg);
            rowpart += vals[v];
            colpart[v] += vals[v];
        }
        // packed-triu store (uncentered): pos = ob + start(i) + (j - i)
        const size_t rb = ob + triu_start(i) - (size_t)i;
        #pragma unroll
        for (int v = 0; v < 4; v++) {
            const int j = j0 + tx * 4 + v;
            if (!diag || j >= i) out[rb + j] = vals[v];
        }
        // reduce rowpart across tx (16 lanes of the half-warp share ty)
        #pragma unroll
        for (int off = 8; off > 0; off >>= 1)
            rowpart += __shfl_xor_sync(0xffffffffu, rowpart, off, 16);
        if (tx == 0) sr[ty * 4 + u] = rowpart;   // unique writer per (ty,u)
    }
    if (!diag) {
        #pragma unroll
        for (int v = 0; v < 4; v++)
            atomicAdd(&sc[tx * 4 + v], colpart[v]);   // 16 ty contributors
    }
    __syncthreads();

    if (tid < 64)
        atomicAdd(&g_s[b * DIMV + i0 + tid], sr[tid]);
    if (!diag && tid >= 64 && tid < 128)
        atomicAdd(&g_s[b * DIMV + j0 + (tid - 64)], sc[tid - 64]);
}

// ---------------------------------------------------------------------------
// K2: grand sum per batch = sum_i s[b][i]. One block per batch.
// ---------------------------------------------------------------------------
__global__ void k_grand() {
    __shared__ float sh[256];
    const int b = blockIdx.x;
    const int tid = threadIdx.x;
    float s = 0.f;
    for (int i = tid; i < DIMV; i += 256) s += g_s[b * DIMV + i];
    sh[tid] = s;
    __syncthreads();
    for (int off = 128; off > 0; off >>= 1) {
        if (tid < off) sh[tid] += sh[tid + off];
        __syncthreads();
    }
    if (tid == 0) g_grand[b] = sh[0];
}

// ---------------------------------------------------------------------------
// K3: in-place double-centering over the packed triu in out.
// grid (DIMV, NB), block 256. Row i holds j = i..DIMV-1 contiguously.
// ---------------------------------------------------------------------------
__global__ void k_out(float* __restrict__ out) {
    const int i = blockIdx.x;
    const int b = blockIdx.y;
    const float inv = 1.f / (float)DIMV;
    const float inv2 = inv * inv;
    const float si = g_s[b * DIMV + i];
    const float gm = g_grand[b] * inv2;
    const float* sv = g_s + b * DIMV;
    float* row = out + (size_t)b * OUT_PER_B + triu_start(i);
    const int len = DIMV - i;
    for (int e = threadIdx.x; e < len; e += 256) {
        const int j = i + e;
        row[e] = row[e] - (si + sv[j]) * inv + gm;
    }
}

// ---------------------------------------------------------------------------
extern "C" void kernel_launch(void* const* d_in, const int* in_sizes, int n_in,
                              void* d_out, int out_size) {
    const float* x = (const float*)d_in[0];
    const float* t = (const float*)d_in[1];
    float* out = (float*)d_out;

    k_prep<<<(NB * DIMV) / 8, 256>>>(x, t);
    k_gemm_dcov<<<dim3(55, NB), 256>>>(x, out);
    k_grand<<<NB, 256>>>();
    k_out<<<dim3(DIMV, NB), 256>>>(out);
}